// round 1
// baseline (speedup 1.0000x reference)
#include <cuda_runtime.h>
#include <cstdint>

// ---------------- packed f32x2 helpers (Blackwell) ----------------
__device__ __forceinline__ unsigned long long f2x_mul(unsigned long long a, unsigned long long b) {
    unsigned long long d;
    asm("mul.rn.f32x2 %0, %1, %2;" : "=l"(d) : "l"(a), "l"(b));
    return d;
}
__device__ __forceinline__ unsigned long long f2x_fma(unsigned long long a, unsigned long long b, unsigned long long c) {
    unsigned long long d;
    asm("fma.rn.f32x2 %0, %1, %2, %3;" : "=l"(d) : "l"(a), "l"(b), "l"(c));
    return d;
}
__device__ __forceinline__ unsigned long long f2x_add(unsigned long long a, unsigned long long b) {
    unsigned long long d;
    asm("add.rn.f32x2 %0, %1, %2;" : "=l"(d) : "l"(a), "l"(b));
    return d;
}
__device__ __forceinline__ unsigned long long f2x_pack(float lo, float hi) {
    unsigned long long d;
    asm("mov.b64 %0, {%1, %2};" : "=l"(d) : "r"(__float_as_uint(lo)), "r"(__float_as_uint(hi)));
    return d;
}
__device__ __forceinline__ void f2x_unpack(float& lo, float& hi, unsigned long long v) {
    unsigned int l, h;
    asm("mov.b64 {%0, %1}, %2;" : "=r"(l), "=r"(h) : "l"(v));
    lo = __uint_as_float(l);
    hi = __uint_as_float(h);
}

// Cody-Waite reduction of phase to ~[-pi, pi]; exact for |phase| <~ 25000
__device__ __forceinline__ float red2pi(float ph) {
    float q = rintf(ph * 0.15915494309f);       // 1/(2*pi)
    ph = fmaf(q, -6.28125f, ph);                // 2*pi hi (12-bit mantissa, product exact)
    ph = fmaf(q, -1.93530717e-3f, ph);          // 2*pi lo
    return ph;
}

// ---------------- main kernel: one block = one head h ----------------
// Block = 64 threads. Thread t computes out[h, t + 64k] for k = 0..STEPS-1 via
// the real 2nd-order recurrence  u_k = a*u_{k-1} + b*u_{k-2}  per mode n,
// with a = 2 Re(W), b = -|W|^2, W = exp(dtA * 64). 32 modes packed as 16 f32x2 lanes.
template <int STEPS>
__global__ __launch_bounds__(64) void s4d_kernel(
    const float* __restrict__ log_dt,
    const float* __restrict__ Cr,          // (H, 32, 2)
    const float* __restrict__ logAre,      // (H, 32)
    const float* __restrict__ Aimag,       // (H, 32)
    float* __restrict__ out, int L)
{
    const int h = blockIdx.x;
    const int tid = threadIdx.x;

    __shared__ float4 sp1[32];  // {a, b, winv_re, winv_im}
    __shared__ float4 sp2[32];  // {cd_re, cd_im, dta_re, dta_im}

    if (tid < 32) {
        const int n = tid;
        const float dt  = __expf(log_dt[h]);
        const float Are = -__expf(logAre[h * 32 + n]);
        const float Ai  = Aimag[h * 32 + n];
        const float dre = Are * dt;
        const float dim = Ai * dt;

        // exp(dtA) (small args: |dim| <= ~10)
        float s1, c1;
        __sincosf(dim, &s1, &c1);
        const float e1 = __expf(dre);
        const float numre = fmaf(e1, c1, -1.0f);
        const float numim = e1 * s1;

        // Cd = Cc * (exp(dtA) - 1) / A  =  Cc * num * conj(A) / |A|^2
        const float inv  = __frcp_rn(fmaf(Are, Are, Ai * Ai));
        const float ccre = Cr[(h * 32 + n) * 2 + 0];
        const float ccim = Cr[(h * 32 + n) * 2 + 1];
        const float tre = ccre * numre - ccim * numim;
        const float tim = ccre * numim + ccim * numre;
        const float cdre = (tre * Are + tim * Ai) * inv;
        const float cdim = (tim * Are - tre * Ai) * inv;

        // W = exp(dtA * 64)
        const float phT = red2pi(dim * 64.0f);
        float sT, cT;
        __sincosf(phT, &sT, &cT);
        const float eT  = __expf(dre * 64.0f);   // >= exp(-3.2), no underflow
        const float Wre = eT * cT;
        const float Wim = eT * sT;
        const float ib  = __frcp_rn(eT * eT);    // 1/|W|^2

        sp1[n] = make_float4(2.0f * Wre, -eT * eT, Wre * ib, -Wim * ib);
        sp2[n] = make_float4(cdre, cdim, dre, dim);
    }
    __syncthreads();

    unsigned long long X1[16], X2[16], A2[16], B2[16];
    const float tf = (float)tid;

    #pragma unroll
    for (int p = 0; p < 16; p++) {
        float x1v[2], x2v[2], av[2], bv[2];
        #pragma unroll
        for (int j = 0; j < 2; j++) {
            const int n = 2 * p + j;
            const float4 q1 = sp1[n];
            const float4 q2 = sp2[n];
            // z = Cd * exp(dtA * tid)
            const float ph = red2pi(q2.w * tf);
            float s, c;
            __sincosf(ph, &s, &c);
            const float r  = __expf(q2.z * tf);   // >= exp(-3.15)
            const float er = r * c;
            const float ei = r * s;
            const float zre = q2.x * er - q2.y * ei;
            const float zim = q2.x * ei + q2.y * er;
            x1v[j] = zre;                              // s(tid)
            x2v[j] = zre * q1.z - zim * q1.w;          // s(tid - 64) = Re(z * W^-1)
            av[j]  = q1.x;
            bv[j]  = q1.y;
        }
        X1[p] = f2x_pack(x1v[0], x1v[1]);
        X2[p] = f2x_pack(x2v[0], x2v[1]);
        A2[p] = f2x_pack(av[0],  av[1]);
        B2[p] = f2x_pack(bv[0],  bv[1]);
    }

    float* op = out + (size_t)h * L + tid;

    #pragma unroll
    for (int k = 0; k < STEPS; k++) {
        unsigned long long acc = 0ull;  // packed (0.0f, 0.0f)
        #pragma unroll
        for (int p = 0; p < 16; p++) {
            acc = f2x_add(acc, X1[p]);
            const unsigned long long t  = f2x_mul(B2[p], X2[p]);
            const unsigned long long xn = f2x_fma(A2[p], X1[p], t);
            X2[p] = X1[p];
            X1[p] = xn;
        }
        float lo, hi;
        f2x_unpack(lo, hi, acc);
        op[(size_t)k * 64] = 2.0f * (lo + hi);
    }
}

// ---------------- generic fallback (any H, N2, L) ----------------
__global__ void s4d_fallback(
    const float* __restrict__ log_dt,
    const float* __restrict__ Cr,
    const float* __restrict__ logAre,
    const float* __restrict__ Aimag,
    float* __restrict__ out, int H, int N2, int L)
{
    const long long idx = (long long)blockIdx.x * blockDim.x + threadIdx.x;
    if (idx >= (long long)H * L) return;
    const int h = (int)(idx / L);
    const int l = (int)(idx % L);
    const float dt = __expf(log_dt[h]);
    const float lf = (float)l;
    float acc = 0.0f;
    for (int n = 0; n < N2; n++) {
        const float Are = -__expf(logAre[h * N2 + n]);
        const float Ai  = Aimag[h * N2 + n];
        const float dre = Are * dt;
        const float dim = Ai * dt;
        float s1, c1;
        __sincosf(dim, &s1, &c1);
        const float e1 = __expf(dre);
        const float numre = fmaf(e1, c1, -1.0f);
        const float numim = e1 * s1;
        const float inv  = __frcp_rn(fmaf(Are, Are, Ai * Ai));
        const float ccre = Cr[(h * N2 + n) * 2 + 0];
        const float ccim = Cr[(h * N2 + n) * 2 + 1];
        const float tre = ccre * numre - ccim * numim;
        const float tim = ccre * numim + ccim * numre;
        const float cdre = (tre * Are + tim * Ai) * inv;
        const float cdim = (tim * Are - tre * Ai) * inv;
        const float ph = red2pi(dim * lf);
        float s, c;
        __sincosf(ph, &s, &c);
        const float r = __expf(dre * lf);
        acc += r * (cdre * c - cdim * s);
    }
    out[idx] = 2.0f * acc;
}

extern "C" void kernel_launch(void* const* d_in, const int* in_sizes, int n_in,
                              void* d_out, int out_size)
{
    const float* log_dt = (const float*)d_in[0];
    const float* Cr     = (const float*)d_in[1];
    const float* lar    = (const float*)d_in[2];
    const float* aim    = (const float*)d_in[3];
    float* out = (float*)d_out;

    const int H  = in_sizes[0];
    const int N2 = (H > 0) ? in_sizes[2] / H : 0;
    const int L  = (H > 0) ? out_size / H : 0;

    if (N2 == 32 && L == 2048) {
        s4d_kernel<32><<<H, 64>>>(log_dt, Cr, lar, aim, out, L);
    } else {
        const long long total = (long long)H * L;
        const int blocks = (int)((total + 127) / 128);
        s4d_fallback<<<blocks, 128>>>(log_dt, Cr, lar, aim, out, H, N2, L);
    }
}